// round 5
// baseline (speedup 1.0000x reference)
#include <cuda_runtime.h>
#include <math.h>

#define B_ 64
#define T_ 2048
#define I_ 64
#define S_ 128
#define O_ 64
#define LN_EPS 1e-5f
#define NSEG 8
#define SEGT (T_/NSEG)
#define TP 2052

typedef unsigned long long ull;

__device__ float g_GX[2ull*B_*TP*S_];
__device__ float g_H [B_*T_*S_];
__device__ float g_xsum[B_*I_];
__device__ float g_boSum[B_*O_];
__device__ float g_boSsq[B_*O_];
__device__ float g_S1, g_S2, g_SA;

__device__ __forceinline__ ull pack2(float lo, float hi) {
    ull r; asm("mov.b64 %0,{%1,%2};" : "=l"(r) : "f"(lo), "f"(hi)); return r;
}
__device__ __forceinline__ void unpack2(ull v, float &lo, float &hi) {
    asm("mov.b64 {%0,%1},%2;" : "=f"(lo), "=f"(hi) : "l"(v));
}
__device__ __forceinline__ ull ffma2(ull a, ull b, ull c) {
    ull d; asm("fma.rn.f32x2 %0,%1,%2,%3;" : "=l"(d) : "l"(a), "l"(b), "l"(c)); return d;
}

__global__ void zeroK() {
    int i = blockIdx.x * blockDim.x + threadIdx.x;
    if (i < B_*O_) { g_boSum[i] = 0.f; g_boSsq[i] = 0.f; }
    if (i < B_*I_) g_xsum[i] = 0.f;
    if (i == 0) { g_S1 = 0.f; g_S2 = 0.f; g_SA = 0.f; }
}

__global__ __launch_bounds__(256) void gateK(
    const float* __restrict__ x, const float* __restrict__ Wsel,
    const float* __restrict__ bsel, const float* __restrict__ Bm)
{
    __shared__ __align__(16) float xs[4][I_];
    __shared__ __align__(16) float ysm[4][2*S_];
    int tid = threadIdx.x;
    bool isG = tid < S_;
    int s = isG ? tid : tid - S_;
    const float* wrow = isG ? (Wsel + s*I_) : (Bm + s*I_);
    ull w2[I_/2];
#pragma unroll
    for (int k = 0; k < I_/2; k++) w2[k] = pack2(wrow[2*k], wrow[2*k+1]);
    float bias = isG ? bsel[s] : 0.f;

    int b  = blockIdx.x >> 3;
    int t0 = (blockIdx.x & 7) * 256;
    const float* xrow = x + ((size_t)b*T_ + t0)*I_;
    float2* outp = ((float2*)g_GX) + (size_t)b*TP*S_;
    float xacc = 0.f;

    for (int g = 0; g < 256; g += 4) {
        { int r = tid >> 6, i = tid & 63;
          xs[r][i] = xrow[(g + r)*I_ + i]; }
        __syncthreads();
#pragma unroll
        for (int r = 0; r < 4; r++) {
            const ull* xv = (const ull*)xs[r];
            ull a0 = 0, a1 = 0, a2 = 0, a3 = 0;
#pragma unroll
            for (int k = 0; k < I_/2; k += 4) {
                a0 = ffma2(w2[k+0], xv[k+0], a0);
                a1 = ffma2(w2[k+1], xv[k+1], a1);
                a2 = ffma2(w2[k+2], xv[k+2], a2);
                a3 = ffma2(w2[k+3], xv[k+3], a3);
            }
            float p,q,u,v,e,f,m,n;
            unpack2(a0,p,q); unpack2(a1,u,v); unpack2(a2,e,f); unpack2(a3,m,n);
            float dot = ((p+q)+(u+v)) + ((e+f)+(m+n));
            if (isG) ysm[r][2*s]     = 1.f / (1.f + __expf(-(dot + bias)));
            else     ysm[r][2*s + 1] = dot;
        }
        if (tid < 64) xacc += (xs[0][tid]+xs[1][tid]) + (xs[2][tid]+xs[3][tid]);
        __syncthreads();
        const float2* fy = (const float2*)ysm;
#pragma unroll
        for (int rr = 0; rr < 2; rr++) {
            int idx = tid + rr*256;
            outp[(size_t)(t0 + g + (idx >> 7))*S_ + (idx & 127)] = fy[idx];
        }
    }
    if (tid < 64) atomicAdd(&g_xsum[b*64 + tid], xacc);
}

__global__ __launch_bounds__(128) void selFin(
    const float* __restrict__ Wsel, const float* __restrict__ bsel)
{
    __shared__ float part[4];
    int tid = threadIdx.x, b = blockIdx.x;
    float acc = bsel[tid];
    const float invT = 1.0f/(float)T_;
    const float* w  = Wsel + tid*I_;
    const float* xm = g_xsum + b*I_;
#pragma unroll 8
    for (int k = 0; k < I_; k++) acc += xm[k]*invT*w[k];
    float sg = 1.f/(1.f + __expf(-acc));
#pragma unroll
    for (int off = 16; off > 0; off >>= 1) sg += __shfl_xor_sync(0xffffffffu, sg, off);
    if ((tid & 31) == 0) part[tid >> 5] = sg;
    __syncthreads();
    if (tid == 0) atomicAdd(&g_SA, (part[0]+part[1]) + (part[2]+part[3]));
}

// recurrence: 288 threads. warps 0-7: half-dots (+ q0 epilogue); warp 8: LN stats only.
__global__ __launch_bounds__(288, 1) void recK(
    const float* __restrict__ A, const float* __restrict__ gamma,
    const float* __restrict__ beta)
{
    __shared__ __align__(16) float hbuf[2][136];   // halves at +0 / +68
    __shared__ __align__(16) float dpart[S_];
    __shared__ __align__(16) float2 red;
    int tid = threadIdx.x, b = blockIdx.x;
    int wid = tid >> 5, lane = tid & 31;
    bool isStat = (wid == 8);
    int s = tid & 127, q = (tid >> 7) & 1;
    int hoff = s + ((s & 64) >> 4);

    float gam_s = 0.f, bet_s = 0.f, agS = 0.f, abv = 0.f, gamS = 0.f;
    ull a2[32];
    if (!isStat) {
        gam_s = gamma[s]; bet_s = beta[s];
        gamS = gam_s * (1.f/S_);
        if (!q) {
            const float* ar = A + s*S_;
#pragma unroll 16
            for (int k = 0; k < S_; k++) {
                agS += ar[k]*gamma[k]; abv += ar[k]*beta[k];
            }
            agS *= (1.f/S_);
        }
        const float* ar = A + s*S_ + q*64;
        const float* gm = gamma + q*64;
#pragma unroll
        for (int k = 0; k < 32; k++)
            a2[k] = pack2(ar[2*k]*gm[2*k], ar[2*k+1]*gm[2*k+1]);
    }

    if (tid < 136) { hbuf[0][tid] = 0.f; hbuf[1][tid] = 0.f; }
    if (tid == 0) red = make_float2(0.f, 0.f);

    const float2* GX = ((const float2*)g_GX) + (size_t)b*TP*S_ + s;
    float* Hp = g_H + (size_t)b*T_*S_ + s;
    float2 gx[4];
    if (!isStat && !q) {
#pragma unroll
        for (int j = 0; j < 4; j++) gx[j] = GX[(size_t)j*S_];
    }
    float hbmine = 0.f;
    int statoff = (lane < 16) ? 4*lane : 4*lane + 4;  // skip pad at [64..67]
    __syncthreads();

    int cur = 0;
#pragma unroll 2
    for (int t = 0; t < T_; t++) {
        if (isStat) {
            float4 hv4 = *(const float4*)&hbuf[cur][statoff];
            float s1 = (hv4.x + hv4.y) + (hv4.z + hv4.w);
            float s2 = (hv4.x*hv4.x + hv4.y*hv4.y) + (hv4.z*hv4.z + hv4.w*hv4.w);
#pragma unroll
            for (int off = 16; off > 0; off >>= 1) {
                s1 += __shfl_xor_sync(0xffffffffu, s1, off);
                s2 += __shfl_xor_sync(0xffffffffu, s2, off);
            }
            if (lane == 0) red = make_float2(s1, s2);
            __syncthreads();   // #1
            __syncthreads();   // #2
        } else {
            float2 gxv = make_float2(0.f, 0.f);
            float abx = 0.f, preh = 0.f;
            if (!q) {
                gxv = gx[t & 3];
                gx[t & 3] = GX[(size_t)(t + 4)*S_];
                abx = (t > 0) ? (abv + gxv.y) : gxv.y;
                preh = hbmine * gam_s;
            }
            const ulonglong2* hv = (const ulonglong2*)(&hbuf[cur][q*68]);
            ull ac0 = 0, ac1 = 0, ac2 = 0, ac3 = 0;
#pragma unroll
            for (int i = 0; i < 16; i += 4) {
                ulonglong2 p = hv[i], r = hv[i+1], u = hv[i+2], v = hv[i+3];
                ac0 = ffma2(a2[2*i+0], p.x, ac0); ac1 = ffma2(a2[2*i+1], p.y, ac1);
                ac2 = ffma2(a2[2*i+2], r.x, ac2); ac3 = ffma2(a2[2*i+3], r.y, ac3);
                ac0 = ffma2(a2[2*i+4], u.x, ac0); ac1 = ffma2(a2[2*i+5], u.y, ac1);
                ac2 = ffma2(a2[2*i+6], v.x, ac2); ac3 = ffma2(a2[2*i+7], v.y, ac3);
            }
            float p0,p1,p2,p3,p4,p5,p6,p7;
            unpack2(ac0,p0,p1); unpack2(ac1,p2,p3); unpack2(ac2,p4,p5); unpack2(ac3,p6,p7);
            float dmine = ((p0+p1)+(p2+p3)) + ((p4+p5)+(p6+p7));
            if (q) dpart[s] = dmine;
            __syncthreads();   // #1: stats + partner half-dots visible

            if (!q) {
                float2 rr = red;
                float sum = rr.x, ssq = rr.y;
                float mu  = sum * (1.f/S_);
                float ve  = fmaf(ssq, 1.f/S_, LN_EPS) - mu*mu;
                float rin = rsqrtf(ve);
                float dfull = dmine + dpart[s];
                float hpn = (t > 0) ? fmaf(fmaf(-sum, gamS, preh), rin, bet_s) : 0.f;
                float nextraw = fmaf(fmaf(-sum, agS, dfull), rin, abx);
                float hb = fmaf(gxv.x, nextraw - hpn, hpn);
                if (t > 0) Hp[(size_t)(t-1)*S_] = hpn;
                hbmine = hb;
                hbuf[cur ^ 1][hoff] = hb;
            }
            __syncthreads();   // #2: new state visible
        }
        cur ^= 1;
    }

    // final LN + store of h_{T-1}
    if (isStat) {
        float4 hv4 = *(const float4*)&hbuf[cur][statoff];
        float s1 = (hv4.x + hv4.y) + (hv4.z + hv4.w);
        float s2 = (hv4.x*hv4.x + hv4.y*hv4.y) + (hv4.z*hv4.z + hv4.w*hv4.w);
#pragma unroll
        for (int off = 16; off > 0; off >>= 1) {
            s1 += __shfl_xor_sync(0xffffffffu, s1, off);
            s2 += __shfl_xor_sync(0xffffffffu, s2, off);
        }
        if (lane == 0) red = make_float2(s1, s2);
    }
    __syncthreads();
    if (!isStat && !q) {
        float2 rr = red;
        float sum = rr.x, ssq = rr.y;
        float mu  = sum * (1.f/S_);
        float ve  = fmaf(ssq, 1.f/S_, LN_EPS) - mu*mu;
        float rin = rsqrtf(ve);
        Hp[(size_t)(T_-1)*S_] = fmaf(fmaf(-sum, gamS, hbmine*gam_s), rin, bet_s);
    }
}

__global__ void outK(const float* __restrict__ x, const float* __restrict__ C,
                     const float* __restrict__ D, float* __restrict__ out)
{
    extern __shared__ __align__(16) char smraw[];
    ull*   Cp = (ull*)smraw;
    ull*   Dp = Cp + 64*64;
    float* Hs = (float*)(Dp + 32*64);
    float* xs = Hs + 4*128;
    float* Ys = xs + 4*64;
    float* yp = Ys + 4*64;

    int tid = threadIdx.x;
    int b = blockIdx.x >> 3;
    int seg = blockIdx.x & 7;
    int tl = tid >> 6, o = tid & 63;
    int t0 = seg * SEGT;

    for (int idx = tid; idx < 64*64; idx += 256) {
        int k = idx >> 6, oo = idx & 63;
        Cp[idx] = pack2(C[oo*S_ + 2*k], C[oo*S_ + 2*k + 1]);
    }
    for (int idx = tid; idx < 32*64; idx += 256) {
        int k = idx >> 6, oo = idx & 63;
        Dp[idx] = pack2(D[oo*I_ + 2*k], D[oo*I_ + 2*k + 1]);
    }
    if (tid < 64) yp[tid] = 0.f;
    __syncthreads();

    if (seg > 0) {
        if (tid < 128) Hs[tid] = g_H[((size_t)b*T_ + (t0-1))*S_ + tid];
        if (tid >= 128 && tid < 192) xs[tid-128] = x[((size_t)b*T_ + (t0-1))*I_ + (tid-128)];
        __syncthreads();
        if (tid < 64) {
            const ull* hv = (const ull*)Hs;
            ull ac0 = 0, ac1 = 0;
#pragma unroll
            for (int k = 0; k < 64; k += 2) {
                ac0 = ffma2(hv[k],   Cp[k*64 + tid],     ac0);
                ac1 = ffma2(hv[k+1], Cp[(k+1)*64 + tid], ac1);
            }
            const ull* xv = (const ull*)xs;
#pragma unroll
            for (int k = 0; k < 32; k += 2) {
                ac0 = ffma2(xv[k],   Dp[k*64 + tid],     ac0);
                ac1 = ffma2(xv[k+1], Dp[(k+1)*64 + tid], ac1);
            }
            float u,v,e,f; unpack2(ac0,u,v); unpack2(ac1,e,f);
            yp[tid] = (u+v)+(e+f);
        }
    }
    __syncthreads();

    float boS = 0.f, boQ = 0.f;
    float nrmAcc = 0.f, difAcc = 0.f;
    int w = tid >> 5, lane = tid & 31;

    for (int g = 0; g < SEGT/4; g++) {
        int tbase = t0 + g*4;
        Hs[tid]       = g_H[((size_t)b*T_ + tbase + (tid >> 7))    *S_ + (tid & 127)];
        Hs[tid + 256] = g_H[((size_t)b*T_ + tbase + 2 + (tid >> 7))*S_ + (tid & 127)];
        xs[tid]       = x  [((size_t)b*T_ + tbase + (tid >> 6))    *I_ + (tid & 63)];
        __syncthreads();

        float y;
        {
            const ull* hv = (const ull*)(Hs + tl*128);
            ull ac0 = 0, ac1 = 0;
#pragma unroll
            for (int k = 0; k < 64; k += 2) {
                ac0 = ffma2(hv[k],   Cp[k*64 + o],     ac0);
                ac1 = ffma2(hv[k+1], Cp[(k+1)*64 + o], ac1);
            }
            const ull* xv = (const ull*)(xs + tl*64);
#pragma unroll
            for (int k = 0; k < 32; k += 2) {
                ac0 = ffma2(xv[k],   Dp[k*64 + o],     ac0);
                ac1 = ffma2(xv[k+1], Dp[(k+1)*64 + o], ac1);
            }
            float u,v,e,f; unpack2(ac0,u,v); unpack2(ac1,e,f);
            y = (u+v)+(e+f);
        }
        Ys[tl*64 + o] = y;
        boS += y; boQ += y*y;
        if (tbase + tl == T_ - 1) out[b*O_ + o] = y;
        __syncthreads();

        if (w < 4) {
            float y0 = Ys[w*64 + lane], y1 = Ys[w*64 + lane + 32];
            float p0, p1;
            if (w == 0) { p0 = yp[lane]; p1 = yp[lane + 32]; }
            else        { p0 = Ys[(w-1)*64 + lane]; p1 = Ys[(w-1)*64 + lane + 32]; }
            float sn = y0*y0 + y1*y1;
            float d0 = y0 - p0, d1 = y1 - p1;
            float dn = d0*d0 + d1*d1;
#pragma unroll
            for (int off = 16; off > 0; off >>= 1) {
                sn += __shfl_xor_sync(0xffffffffu, sn, off);
                dn += __shfl_xor_sync(0xffffffffu, dn, off);
            }
            if (lane == 0) {
                nrmAcc += sqrtf(sn);
                if (tbase + w > 0) difAcc += sqrtf(dn);
            }
        }
        __syncthreads();
        if (tid < 64) yp[tid] = Ys[3*64 + tid];
        __syncthreads();
    }

    if (w < 4 && lane == 0) {
        atomicAdd(&g_S2, nrmAcc);
        atomicAdd(&g_S1, difAcc);
    }
    __syncthreads();
    Ys[tid] = boS;
    __syncthreads();
    if (tl == 0) atomicAdd(&g_boSum[b*64 + o], (Ys[o] + Ys[64+o]) + (Ys[128+o] + Ys[192+o]));
    __syncthreads();
    Ys[tid] = boQ;
    __syncthreads();
    if (tl == 0) atomicAdd(&g_boSsq[b*64 + o], (Ys[o] + Ys[64+o]) + (Ys[128+o] + Ys[192+o]));
}

__global__ void finK(float* __restrict__ out)
{
    __shared__ float part[8];
    int tid = threadIdx.x;
    float acc = 0.f;
    for (int idx = tid; idx < B_*O_; idx += 256) {
        float sum = g_boSum[idx], ssq = g_boSsq[idx];
        float var = (ssq - sum*sum*(1.f/T_)) * (1.f/(T_ - 1));
        acc += sqrtf(fmaxf(var, 0.f));
    }
#pragma unroll
    for (int off = 16; off > 0; off >>= 1) acc += __shfl_xor_sync(0xffffffffu, acc, off);
    if ((tid & 31) == 0) part[tid >> 5] = acc;
    __syncthreads();
    if (tid == 0) {
        float tot = 0.f;
#pragma unroll
        for (int k = 0; k < 8; k++) tot += part[k];
        out[4096] = 1.f / (1.f + g_S1 / (float)(B_*(T_-1)));
        out[4097] = g_S2 / (float)(B_*T_);
        out[4098] = g_SA / (float)(B_*S_);
        out[4099] = tot  / (float)(B_*O_);
    }
}

extern "C" void kernel_launch(void* const* d_in, const int* in_sizes, int n_in,
                              void* d_out, int out_size)
{
    const float* x     = (const float*)d_in[0];
    const float* A     = (const float*)d_in[1];
    const float* Bm    = (const float*)d_in[2];
    const float* C     = (const float*)d_in[3];
    const float* D     = (const float*)d_in[4];
    const float* Wsel  = (const float*)d_in[5];
    const float* bsel  = (const float*)d_in[6];
    const float* gamma = (const float*)d_in[7];
    const float* beta  = (const float*)d_in[8];
    float* out = (float*)d_out;

    zeroK<<<16, 256>>>();
    gateK<<<B_*8, 256>>>(x, Wsel, bsel, Bm);
    selFin<<<B_, 128>>>(Wsel, bsel);
    recK<<<B_, 288>>>(A, gamma, beta);

    int smem = (64*64 + 32*64)*8 + (4*128 + 4*64 + 4*64 + 64)*4;
    cudaFuncSetAttribute(outK, cudaFuncAttributeMaxDynamicSharedMemorySize, smem);
    outK<<<B_*NSEG, 256, smem>>>(x, C, D, out);
    finK<<<1, 256>>>(out);
}

// round 6
// speedup vs baseline: 1.3313x; 1.3313x over previous
#include <cuda_runtime.h>
#include <math.h>

#define B_ 64
#define T_ 2048
#define I_ 64
#define S_ 128
#define O_ 64
#define LN_EPS 1e-5f
#define NSEG 8
#define SEGT (T_/NSEG)
#define TP 2052

typedef unsigned long long ull;

__device__ float g_GX[2ull*B_*TP*S_];
__device__ float g_H [B_*T_*S_];
__device__ float g_xsum[B_*I_];
__device__ float g_boSum[B_*O_];
__device__ float g_boSsq[B_*O_];
__device__ float g_S1, g_S2, g_SA;

__device__ __forceinline__ ull pack2(float lo, float hi) {
    ull r; asm("mov.b64 %0,{%1,%2};" : "=l"(r) : "f"(lo), "f"(hi)); return r;
}
__device__ __forceinline__ void unpack2(ull v, float &lo, float &hi) {
    asm("mov.b64 {%0,%1},%2;" : "=f"(lo), "=f"(hi) : "l"(v));
}
__device__ __forceinline__ ull ffma2(ull a, ull b, ull c) {
    ull d; asm("fma.rn.f32x2 %0,%1,%2,%3;" : "=l"(d) : "l"(a), "l"(b), "l"(c)); return d;
}

__global__ void zeroK() {
    int i = blockIdx.x * blockDim.x + threadIdx.x;
    if (i < B_*O_) { g_boSum[i] = 0.f; g_boSsq[i] = 0.f; }
    if (i < B_*I_) g_xsum[i] = 0.f;
    if (i == 0) { g_S1 = 0.f; g_S2 = 0.f; g_SA = 0.f; }
}

__global__ __launch_bounds__(256) void gateK(
    const float* __restrict__ x, const float* __restrict__ Wsel,
    const float* __restrict__ bsel, const float* __restrict__ Bm)
{
    __shared__ __align__(16) float xs[4][I_];
    __shared__ __align__(16) float ysm[4][2*S_];
    int tid = threadIdx.x;
    bool isG = tid < S_;
    int s = isG ? tid : tid - S_;
    const float* wrow = isG ? (Wsel + s*I_) : (Bm + s*I_);
    ull w2[I_/2];
#pragma unroll
    for (int k = 0; k < I_/2; k++) w2[k] = pack2(wrow[2*k], wrow[2*k+1]);
    float bias = isG ? bsel[s] : 0.f;

    int b  = blockIdx.x >> 3;
    int t0 = (blockIdx.x & 7) * 256;
    const float* xrow = x + ((size_t)b*T_ + t0)*I_;
    float2* outp = ((float2*)g_GX) + (size_t)b*TP*S_;
    float xacc = 0.f;

    for (int g = 0; g < 256; g += 4) {
        { int r = tid >> 6, i = tid & 63;
          xs[r][i] = xrow[(g + r)*I_ + i]; }
        __syncthreads();
#pragma unroll
        for (int r = 0; r < 4; r++) {
            const ull* xv = (const ull*)xs[r];
            ull a0 = 0, a1 = 0, a2 = 0, a3 = 0;
#pragma unroll
            for (int k = 0; k < I_/2; k += 4) {
                a0 = ffma2(w2[k+0], xv[k+0], a0);
                a1 = ffma2(w2[k+1], xv[k+1], a1);
                a2 = ffma2(w2[k+2], xv[k+2], a2);
                a3 = ffma2(w2[k+3], xv[k+3], a3);
            }
            float p,qf,u,v,e,f,m,n;
            unpack2(a0,p,qf); unpack2(a1,u,v); unpack2(a2,e,f); unpack2(a3,m,n);
            float dot = ((p+qf)+(u+v)) + ((e+f)+(m+n));
            if (isG) ysm[r][2*s]     = 1.f / (1.f + __expf(-(dot + bias)));
            else     ysm[r][2*s + 1] = dot;
        }
        if (tid < 64) xacc += (xs[0][tid]+xs[1][tid]) + (xs[2][tid]+xs[3][tid]);
        __syncthreads();
        const float2* fy = (const float2*)ysm;
#pragma unroll
        for (int rr = 0; rr < 2; rr++) {
            int idx = tid + rr*256;
            outp[(size_t)(t0 + g + (idx >> 7))*S_ + (idx & 127)] = fy[idx];
        }
    }
    if (tid < 64) atomicAdd(&g_xsum[b*64 + tid], xacc);
}

__global__ __launch_bounds__(128) void selFin(
    const float* __restrict__ Wsel, const float* __restrict__ bsel)
{
    __shared__ float part[4];
    int tid = threadIdx.x, b = blockIdx.x;
    float acc = bsel[tid];
    const float invT = 1.0f/(float)T_;
    const float* w  = Wsel + tid*I_;
    const float* xm = g_xsum + b*I_;
#pragma unroll 8
    for (int k = 0; k < I_; k++) acc += xm[k]*invT*w[k];
    float sg = 1.f/(1.f + __expf(-acc));
#pragma unroll
    for (int off = 16; off > 0; off >>= 1) sg += __shfl_xor_sync(0xffffffffu, sg, off);
    if ((tid & 31) == 0) part[tid >> 5] = sg;
    __syncthreads();
    if (tid == 0) atomicAdd(&g_SA, (part[0]+part[1]) + (part[2]+part[3]));
}

// recurrence: 256 threads, lane-paired half-dots, 1 barrier/step, piggybacked LN stats.
// warp w, lane l: s = 16w + (l>>1), q = l&1 owns columns [q*64, q*64+64).
__global__ __launch_bounds__(256, 1) void recK(
    const float* __restrict__ A, const float* __restrict__ gamma,
    const float* __restrict__ beta)
{
    __shared__ __align__(16) float hbuf[2][136];   // upper half at +68 floats (bank-shifted)
    __shared__ __align__(16) float2 red[2][8];     // per-warp (sum, ssq) partials, double-buffered
    int tid = threadIdx.x, b = blockIdx.x;
    int w = tid >> 5, lane = tid & 31;
    int s = (w << 4) + (lane >> 1);
    int q = lane & 1;
    int hoff = s + ((s & 64) >> 4);
    const float invS = 1.f/(float)S_;

    float gam_s = gamma[s], bet_s = beta[s];
    float gamI = gam_s * invS;
    float agI = 0.f, abv = 0.f;
    {
        const float* ar = A + s*S_;
#pragma unroll 16
        for (int k = 0; k < S_; k++) { agI += ar[k]*gamma[k]; abv += ar[k]*beta[k]; }
        agI *= invS;
    }
    ull a2[32];
    {
        const float* ar = A + s*S_ + q*64;
        const float* gm = gamma + q*64;
#pragma unroll
        for (int k = 0; k < 32; k++)
            a2[k] = pack2(ar[2*k]*gm[2*k], ar[2*k+1]*gm[2*k+1]);
    }

    if (tid < 136) { hbuf[0][tid] = 0.f; hbuf[1][tid] = 0.f; }
    if (tid < 16)  ((float2*)red)[tid] = make_float2(0.f, 0.f);

    const float2* GX = ((const float2*)g_GX) + (size_t)b*TP*S_ + s;
    float* Hp = g_H + (size_t)b*T_*S_ + s;
    float2 gx[4];
#pragma unroll
    for (int j = 0; j < 4; j++) gx[j] = GX[(size_t)j*S_];
    float hbmine = 0.f;
    __syncthreads();

    int p = 0;
#pragma unroll 4
    for (int t = 0; t < T_; t++) {
        float2 gxv = gx[t & 3];
        gx[t & 3] = GX[(size_t)(t + 4)*S_];

        // LN stats of hb_{t-1} from per-warp partials (piggybacked on the state barrier)
        const float4* rp = (const float4*)red[p];
        float4 r0 = rp[0], r1 = rp[1], r2 = rp[2], r3 = rp[3];
        float sum = ((r0.x + r0.z) + (r1.x + r1.z)) + ((r2.x + r2.z) + (r3.x + r3.z));
        float ssq = ((r0.y + r0.w) + (r1.y + r1.w)) + ((r2.y + r2.w) + (r3.y + r3.w));
        float mu  = sum * invS;
        float ve  = fmaf(ssq, invS, LN_EPS) - mu*mu;
        float rin = rsqrtf(ve);

        // my 64-column half of the dot over raw hb_{t-1}
        const ulonglong2* hv = (const ulonglong2*)(&hbuf[p][q*68]);
        ull ac0 = 0, ac1 = 0, ac2 = 0, ac3 = 0;
#pragma unroll
        for (int i = 0; i < 16; i += 4) {
            ulonglong2 pv = hv[i], rv = hv[i+1], uv = hv[i+2], vv = hv[i+3];
            ac0 = ffma2(a2[2*i+0], pv.x, ac0); ac1 = ffma2(a2[2*i+1], pv.y, ac1);
            ac2 = ffma2(a2[2*i+2], rv.x, ac2); ac3 = ffma2(a2[2*i+3], rv.y, ac3);
            ac0 = ffma2(a2[2*i+4], uv.x, ac0); ac1 = ffma2(a2[2*i+5], uv.y, ac1);
            ac2 = ffma2(a2[2*i+6], vv.x, ac2); ac3 = ffma2(a2[2*i+7], vv.y, ac3);
        }
        float p0,p1,p2,p3,p4,p5,p6,p7;
        unpack2(ac0,p0,p1); unpack2(ac1,p2,p3); unpack2(ac2,p4,p5); unpack2(ac3,p6,p7);
        float dmine = ((p0+p1)+(p2+p3)) + ((p4+p5)+(p6+p7));
        float dfull = dmine + __shfl_xor_sync(0xffffffffu, dmine, 1);

        float abx  = (t > 0) ? (abv + gxv.y) : gxv.y;
        float preh = hbmine * gam_s;
        float hpn = (t > 0) ? fmaf(fmaf(-sum, gamI, preh), rin, bet_s) : 0.f;
        float nextraw = fmaf(fmaf(-sum, agI, dfull), rin, abx);
        float hb = fmaf(gxv.x, nextraw - hpn, hpn);
        if (t > 0 && !q) Hp[(size_t)(t-1)*S_] = hpn;
        if (!q) hbuf[p ^ 1][hoff] = hb;
        hbmine = hb;

        // per-warp stat partial of hb_t: offsets 16..2 (pairs are duplicates, skip off=1)
        float s1 = hb, s2 = hb*hb;
#pragma unroll
        for (int off = 16; off > 1; off >>= 1) {
            s1 += __shfl_xor_sync(0xffffffffu, s1, off);
            s2 += __shfl_xor_sync(0xffffffffu, s2, off);
        }
        if (lane == 0) red[p ^ 1][w] = make_float2(s1, s2);
        __syncthreads();
        p ^= 1;
    }

    // final normalize + store of h_{T-1}
    {
        const float4* rp = (const float4*)red[p];
        float4 r0 = rp[0], r1 = rp[1], r2 = rp[2], r3 = rp[3];
        float sum = ((r0.x + r0.z) + (r1.x + r1.z)) + ((r2.x + r2.z) + (r3.x + r3.z));
        float ssq = ((r0.y + r0.w) + (r1.y + r1.w)) + ((r2.y + r2.w) + (r3.y + r3.w));
        float mu  = sum * invS;
        float ve  = fmaf(ssq, invS, LN_EPS) - mu*mu;
        float rin = rsqrtf(ve);
        float hpn = fmaf(fmaf(-sum, gamI, hbmine*gam_s), rin, bet_s);
        if (!q) Hp[(size_t)(T_-1)*S_] = hpn;
    }
}

__global__ void outK(const float* __restrict__ x, const float* __restrict__ C,
                     const float* __restrict__ D, float* __restrict__ out)
{
    extern __shared__ __align__(16) char smraw[];
    ull*   Cp = (ull*)smraw;
    ull*   Dp = Cp + 64*64;
    float* Hs = (float*)(Dp + 32*64);
    float* xs = Hs + 4*128;
    float* Ys = xs + 4*64;
    float* yp = Ys + 4*64;

    int tid = threadIdx.x;
    int b = blockIdx.x >> 3;
    int seg = blockIdx.x & 7;
    int tl = tid >> 6, o = tid & 63;
    int t0 = seg * SEGT;

    for (int idx = tid; idx < 64*64; idx += 256) {
        int k = idx >> 6, oo = idx & 63;
        Cp[idx] = pack2(C[oo*S_ + 2*k], C[oo*S_ + 2*k + 1]);
    }
    for (int idx = tid; idx < 32*64; idx += 256) {
        int k = idx >> 6, oo = idx & 63;
        Dp[idx] = pack2(D[oo*I_ + 2*k], D[oo*I_ + 2*k + 1]);
    }
    if (tid < 64) yp[tid] = 0.f;
    __syncthreads();

    if (seg > 0) {
        if (tid < 128) Hs[tid] = g_H[((size_t)b*T_ + (t0-1))*S_ + tid];
        if (tid >= 128 && tid < 192) xs[tid-128] = x[((size_t)b*T_ + (t0-1))*I_ + (tid-128)];
        __syncthreads();
        if (tid < 64) {
            const ull* hv = (const ull*)Hs;
            ull ac0 = 0, ac1 = 0;
#pragma unroll
            for (int k = 0; k < 64; k += 2) {
                ac0 = ffma2(hv[k],   Cp[k*64 + tid],     ac0);
                ac1 = ffma2(hv[k+1], Cp[(k+1)*64 + tid], ac1);
            }
            const ull* xv = (const ull*)xs;
#pragma unroll
            for (int k = 0; k < 32; k += 2) {
                ac0 = ffma2(xv[k],   Dp[k*64 + tid],     ac0);
                ac1 = ffma2(xv[k+1], Dp[(k+1)*64 + tid], ac1);
            }
            float u,v,e,f; unpack2(ac0,u,v); unpack2(ac1,e,f);
            yp[tid] = (u+v)+(e+f);
        }
    }
    __syncthreads();

    float boS = 0.f, boQ = 0.f;
    float nrmAcc = 0.f, difAcc = 0.f;
    int w = tid >> 5, lane = tid & 31;

    for (int g = 0; g < SEGT/4; g++) {
        int tbase = t0 + g*4;
        Hs[tid]       = g_H[((size_t)b*T_ + tbase + (tid >> 7))    *S_ + (tid & 127)];
        Hs[tid + 256] = g_H[((size_t)b*T_ + tbase + 2 + (tid >> 7))*S_ + (tid & 127)];
        xs[tid]       = x  [((size_t)b*T_ + tbase + (tid >> 6))    *I_ + (tid & 63)];
        __syncthreads();

        float y;
        {
            const ull* hv = (const ull*)(Hs + tl*128);
            ull ac0 = 0, ac1 = 0;
#pragma unroll
            for (int k = 0; k < 64; k += 2) {
                ac0 = ffma2(hv[k],   Cp[k*64 + o],     ac0);
                ac1 = ffma2(hv[k+1], Cp[(k+1)*64 + o], ac1);
            }
            const ull* xv = (const ull*)(xs + tl*64);
#pragma unroll
            for (int k = 0; k < 32; k += 2) {
                ac0 = ffma2(xv[k],   Dp[k*64 + o],     ac0);
                ac1 = ffma2(xv[k+1], Dp[(k+1)*64 + o], ac1);
            }
            float u,v,e,f; unpack2(ac0,u,v); unpack2(ac1,e,f);
            y = (u+v)+(e+f);
        }
        Ys[tl*64 + o] = y;
        boS += y; boQ += y*y;
        if (tbase + tl == T_ - 1) out[b*O_ + o] = y;
        __syncthreads();

        if (w < 4) {
            float y0 = Ys[w*64 + lane], y1 = Ys[w*64 + lane + 32];
            float p0, p1;
            if (w == 0) { p0 = yp[lane]; p1 = yp[lane + 32]; }
            else        { p0 = Ys[(w-1)*64 + lane]; p1 = Ys[(w-1)*64 + lane + 32]; }
            float sn = y0*y0 + y1*y1;
            float d0 = y0 - p0, d1 = y1 - p1;
            float dn = d0*d0 + d1*d1;
#pragma unroll
            for (int off = 16; off > 0; off >>= 1) {
                sn += __shfl_xor_sync(0xffffffffu, sn, off);
                dn += __shfl_xor_sync(0xffffffffu, dn, off);
            }
            if (lane == 0) {
                nrmAcc += sqrtf(sn);
                if (tbase + w > 0) difAcc += sqrtf(dn);
            }
        }
        __syncthreads();
        if (tid < 64) yp[tid] = Ys[3*64 + tid];
        __syncthreads();
    }

    if (w < 4 && lane == 0) {
        atomicAdd(&g_S2, nrmAcc);
        atomicAdd(&g_S1, difAcc);
    }
    __syncthreads();
    Ys[tid] = boS;
    __syncthreads();
    if (tl == 0) atomicAdd(&g_boSum[b*64 + o], (Ys[o] + Ys[64+o]) + (Ys[128+o] + Ys[192+o]));
    __syncthreads();
    Ys[tid] = boQ;
    __syncthreads();
    if (tl == 0) atomicAdd(&g_boSsq[b*64 + o], (Ys[o] + Ys[64+o]) + (Ys[128+o] + Ys[192+o]));
}

__global__ void finK(float* __restrict__ out)
{
    __shared__ float part[8];
    int tid = threadIdx.x;
    float acc = 0.f;
    for (int idx = tid; idx < B_*O_; idx += 256) {
        float sum = g_boSum[idx], ssq = g_boSsq[idx];
        float var = (ssq - sum*sum*(1.f/T_)) * (1.f/(T_ - 1));
        acc += sqrtf(fmaxf(var, 0.f));
    }
#pragma unroll
    for (int off = 16; off > 0; off >>= 1) acc += __shfl_xor_sync(0xffffffffu, acc, off);
    if ((tid & 31) == 0) part[tid >> 5] = acc;
    __syncthreads();
    if (tid == 0) {
        float tot = 0.f;
#pragma unroll
        for (int k = 0; k < 8; k++) tot += part[k];
        out[4096] = 1.f / (1.f + g_S1 / (float)(B_*(T_-1)));
        out[4097] = g_S2 / (float)(B_*T_);
        out[4098] = g_SA / (float)(B_*S_);
        out[4099] = tot  / (float)(B_*O_);
    }
}

extern "C" void kernel_launch(void* const* d_in, const int* in_sizes, int n_in,
                              void* d_out, int out_size)
{
    const float* x     = (const float*)d_in[0];
    const float* A     = (const float*)d_in[1];
    const float* Bm    = (const float*)d_in[2];
    const float* C     = (const float*)d_in[3];
    const float* D     = (const float*)d_in[4];
    const float* Wsel  = (const float*)d_in[5];
    const float* bsel  = (const float*)d_in[6];
    const float* gamma = (const float*)d_in[7];
    const float* beta  = (const float*)d_in[8];
    float* out = (float*)d_out;

    zeroK<<<16, 256>>>();
    gateK<<<B_*8, 256>>>(x, Wsel, bsel, Bm);
    selFin<<<B_, 128>>>(Wsel, bsel);
    recK<<<B_, 256>>>(A, gamma, beta);

    int smem = (64*64 + 32*64)*8 + (4*128 + 4*64 + 4*64 + 64)*4;
    cudaFuncSetAttribute(outK, cudaFuncAttributeMaxDynamicSharedMemorySize, smem);
    outK<<<B_*NSEG, 256, smem>>>(x, C, D, out);
    finK<<<1, 256>>>(out);
}